// round 14
// baseline (speedup 1.0000x reference)
#include <cuda_runtime.h>
#include <math.h>
#include <stdint.h>

#define NN 8192
#define HH 128
#define IOU 384
#define DEPS 1e-6f
#define DINL __device__ __forceinline__

// ------------------------- device scratch (no cudaMalloc allowed) -------------------------
__device__ float g_L1[NN*HH], g_L2[NN*HH], g_Lc1[NN*HH], g_Lc2[NN*HH], g_lxp[NN*HH], g_lxs[NN*HH];
__device__ float g_A1[NN*HH], g_A2[NN*HH], g_A3[NN*HH];
__device__ float g_F1[NN*HH], g_F2[NN*HH], g_F3[NN*HH];
__device__ float g_C1[NN*HH], g_C2[NN*HH], g_C3[NN*HH];
__device__ float g_Q1[NN*HH], g_Q2[NN*HH], g_Q3[NN*HH];
__device__ float g_H1P[NN*HH], g_H1S[NN*HH], g_H1E[NN*HH];
__device__ float g_P1[NN*HH], g_P2[NN*HH], g_E3[NN*HH];
__device__ float g_XP[NN*HH], g_XS[NN*HH];
__device__ float4 g_SCL[NN];
__device__ float2 g_QS[NN];
__device__ float g_SCP[NN*8], g_SCS[NN*8], g_SCE[NN*8];
__device__ float g_lhtp[NN*HH], g_lhts[NN*HH], g_hte[NN*HH];
__device__ float g_c1v[NN*HH], g_c2v[NN*HH], g_c3v[NN*HH];
__device__ float g_G1[NN*IOU], g_G2[NN*IOU], g_G3[NN*IOU];

// ------------------------- fast transcendentals (MUFU-based) -------------------------
DINL float ftanh(float x) {                 // overflow-safe, ~1e-6 rel err
    float a = fabsf(x);
    float e = __expf(2.f * a);              // inf for large a -> t = 1
    float t = 1.f - 2.f / (e + 1.f);
    return copysignf(t, x);
}
DINL float fsig(float x) { return 1.f / (1.f + __expf(-x)); }

// ------------------------- warp-distributed vector helpers -------------------------
DINL float wsum(float v) {
#pragma unroll
    for (int o = 16; o; o >>= 1) v += __shfl_xor_sync(0xffffffffu, v, o);
    return v;
}
template<int D> DINL void vld(float* v, const float* p, int ln) {
#pragma unroll
    for (int i = 0; i < D; i++) v[i] = p[ln + 32 * i];
}
template<int D> DINL void vst(float* p, const float* v, int ln) {
#pragma unroll
    for (int i = 0; i < D; i++) p[ln + 32 * i] = v[i];
}
template<int D> DINL float rawsq(const float* v) {
    float s = 0.f;
#pragma unroll
    for (int i = 0; i < D; i++) s += v[i] * v[i];
    return wsum(s);
}
template<int D> DINL float vnorm(const float* v) { return sqrtf(rawsq<D>(v) + 1e-15f); }
template<int D> DINL float vdot(const float* a, const float* b) {
    float s = 0.f;
#pragma unroll
    for (int i = 0; i < D; i++) s += a[i] * b[i];
    return wsum(s);
}

DINL float artanh_c(float u) {
    u = fminf(fmaxf(u, -0.99999f), 0.99999f);
    return 0.5f * __logf((1.f + u) / (1.f - u));
}
DINL float tan_c(float u) { return __tanf(fminf(fmaxf(u, -1.47079f), 1.47079f)); }
template<int S> DINL float artank(float u) { return (S < 0) ? artanh_c(u) : atanf(u); }
template<int S> DINL float tank(float u)   { return (S < 0) ? ftanh(u)    : tan_c(u); }

template<int D, int S> DINL void projk(float* v) {
    if (S < 0) {
        float n = vnorm<D>(v);
        if (n > 0.9999f) {
            float s = 0.9999f / n;
#pragma unroll
            for (int i = 0; i < D; i++) v[i] *= s;
        }
    }
}
template<int D, int S> DINL void logmap0(float* v) {
    float n = vnorm<D>(v);
    float s = artank<S>(n) / n;
#pragma unroll
    for (int i = 0; i < D; i++) v[i] *= s;
}
template<int D, int S> DINL void expmap0(float* v) {
    float n = vnorm<D>(v);
    float s = tank<S>(n) / n;
#pragma unroll
    for (int i = 0; i < D; i++) v[i] *= s;
    projk<D, S>(v);
}
template<int D, int S> DINL void smul_half(float* v) {
    float n = vnorm<D>(v);
    float s = tank<S>(0.5f * artank<S>(n)) / n;
#pragma unroll
    for (int i = 0; i < D; i++) v[i] *= s;
    projk<D, S>(v);
}
template<int D, int S> DINL void pwmul(const float* w, const float* x, float* out) {
    float wx[D];
#pragma unroll
    for (int i = 0; i < D; i++) wx[i] = w[i] * x[i];
    float nx = vnorm<D>(x), nwx = vnorm<D>(wx);
    float s = tank<S>(nwx / nx * artank<S>(nx)) / nwx;
#pragma unroll
    for (int i = 0; i < D; i++) out[i] = s * wx[i];
    projk<D, S>(out);
}
template<int D, int S> DINL void pwmul_scalar_x(const float* csk, float g, float* out) {
    float rn2 = rawsq<D>(csk);
    float nx  = sqrtf(g * g + 1e-15f);
    float nwx = sqrtf(g * g * rn2 + 1e-15f);
    float sc  = tank<S>(nwx / nx * artank<S>(nx)) / nwx * g;
#pragma unroll
    for (int i = 0; i < D; i++) out[i] = sc * csk[i];
    projk<D, S>(out);
}
DINL float safeden(float d) { return d >= 0.f ? fmaxf(d, DEPS) : fminf(d, -DEPS); }
template<int D, int S> DINL void madd(const float* x, const float* y, float* out) {
    float sx = 0.f, sy = 0.f, sxy = 0.f;
#pragma unroll
    for (int i = 0; i < D; i++) { sx += x[i] * x[i]; sy += y[i] * y[i]; sxy += x[i] * y[i]; }
    sx = wsum(sx); sy = wsum(sy); sxy = wsum(sxy);
    const float k = (float)S;
    float a = 1.f - 2.f * k * sxy - k * sy;
    float b = 1.f + k * sx;
    float id = 1.f / safeden(1.f - 2.f * k * sxy + sx * sy);
#pragma unroll
    for (int i = 0; i < D; i++) out[i] = (a * x[i] + b * y[i]) * id;
    projk<D, S>(out);
}
template<int D> DINL void sigv(float* v) {
#pragma unroll
    for (int i = 0; i < D; i++) v[i] = fsig(v[i]);
}
template<int D> DINL void tanhv(float* v) {
#pragma unroll
    for (int i = 0; i < D; i++) v[i] = ftanh(v[i]);
}
template<int D> DINL void vcp(float* d, const float* s) {
#pragma unroll
    for (int i = 0; i < D; i++) d[i] = s[i];
}

DINL float distnorm(float x2, float y2, float qd, float k, bool clipP) {
    float A = 1.f + 2.f * k * qd - k * y2;
    float B = 1.f + k * x2;
    float den = safeden(1.f + 2.f * k * qd + x2 * y2);
    float num2 = fmaxf(A * A * x2 + B * B * y2 - 2.f * A * B * qd, 0.f);
    float nz = sqrtf(num2 / (den * den) + 1e-15f);
    if (clipP) nz = fminf(nz, 0.9999f);
    return nz;
}
DINL void softmax8(float* s) {
    float m = s[0];
#pragma unroll
    for (int k = 1; k < 8; k++) m = fmaxf(m, s[k]);
    float t = 0.f;
#pragma unroll
    for (int k = 0; k < 8; k++) { s[k] = __expf(s[k] - m); t += s[k]; }
    float it = 1.f / t;
#pragma unroll
    for (int k = 0; k < 8; k++) s[k] *= it;
}

// ------------------------- k_prep -------------------------
__global__ void k_prep(const float* __restrict__ x, const float* __restrict__ h1,
                       const float* __restrict__ h2, const float* __restrict__ c1,
                       const float* __restrict__ c2) {
    int w = (blockIdx.x * blockDim.x + threadIdx.x) >> 5;
    int ln = threadIdx.x & 31;
    if (w >= NN) return;
    const int off = w * HH;
    float v[4];
    vld<4>(v, h1 + off, ln); logmap0<4, -1>(v); vst<4>(g_L1 + off, v, ln);
    vld<4>(v, h2 + off, ln); logmap0<4, 1>(v);  vst<4>(g_L2 + off, v, ln);
    vld<4>(v, c1 + off, ln); logmap0<4, -1>(v); vst<4>(g_Lc1 + off, v, ln);
    vld<4>(v, c2 + off, ln); logmap0<4, 1>(v);  vst<4>(g_Lc2 + off, v, ln);
    vld<4>(v, x + off, ln);  expmap0<4, -1>(v); logmap0<4, -1>(v); vst<4>(g_lxp + off, v, ln);
    vld<4>(v, x + off, ln);  expmap0<4, 1>(v);  logmap0<4, 1>(v);  vst<4>(g_lxs + off, v, ln);
}

// ------------------------- tf32 tensor-core batched GEMM -------------------------
struct GemmJobs {
    const float* A[12];
    const float* W[12];
    const float* B[12];
    float* C[12];
};

#define GP 36
#define GBUF (128 * GP)

DINL uint32_t f2tf32(float f) {
    uint32_t o;
    asm("cvt.rna.tf32.f32 %0, %1;" : "=r"(o) : "f"(f));
    return o;
}
DINL void mma_tf32(float* c, const uint32_t* a, const uint32_t* b) {
    asm volatile(
        "mma.sync.aligned.m16n8k8.row.col.f32.tf32.tf32.f32 "
        "{%0,%1,%2,%3}, {%4,%5,%6,%7}, {%8,%9}, {%0,%1,%2,%3};"
        : "+f"(c[0]), "+f"(c[1]), "+f"(c[2]), "+f"(c[3])
        : "r"(a[0]), "r"(a[1]), "r"(a[2]), "r"(a[3]), "r"(b[0]), "r"(b[1]));
}

__global__ __launch_bounds__(256) void gemm_tf32(GemmJobs J, int Ncols) {
    extern __shared__ float sm[];
    float* As = sm;
    float* Bs = sm + 2 * GBUF;

    const int jb = blockIdx.z;
    const float* __restrict__ A = J.A[jb];
    const float* __restrict__ W = J.W[jb];
    const float* __restrict__ Bb = J.B[jb];
    float* __restrict__ C = J.C[jb];
    const int rowBase = blockIdx.x * 128;
    const int colBase = blockIdx.y * 128;

    const int tid = threadIdx.x, lane = tid & 31, warp = tid >> 5;
    const int wm = (warp & 1) * 64;
    const int wn = (warp >> 1) * 32;
    const int lr = lane >> 2;
    const int lc = lane & 3;

    const int ldRow = tid >> 3;
    const int ldK   = (tid & 7) * 4;

    float acc[4][4][4];
#pragma unroll
    for (int mf = 0; mf < 4; mf++)
#pragma unroll
        for (int nf = 0; nf < 4; nf++)
#pragma unroll
            for (int q = 0; q < 4; q++) acc[mf][nf][q] = 0.f;

    {
        float* Ad = As;
        float* Bd = Bs;
#pragma unroll
        for (int i = 0; i < 4; i++) {
            int r = ldRow + 32 * i;
            float4 av = *(const float4*)(A + (rowBase + r) * 128 + ldK);
            float4 bv = *(const float4*)(W + (colBase + r) * 128 + ldK);
            float* ap = Ad + r * GP + ldK;
            float* bp = Bd + r * GP + ldK;
            ((uint32_t*)ap)[0] = f2tf32(av.x); ((uint32_t*)ap)[1] = f2tf32(av.y);
            ((uint32_t*)ap)[2] = f2tf32(av.z); ((uint32_t*)ap)[3] = f2tf32(av.w);
            ((uint32_t*)bp)[0] = f2tf32(bv.x); ((uint32_t*)bp)[1] = f2tf32(bv.y);
            ((uint32_t*)bp)[2] = f2tf32(bv.z); ((uint32_t*)bp)[3] = f2tf32(bv.w);
        }
    }
    __syncthreads();

#pragma unroll
    for (int kc = 0; kc < 4; kc++) {
        float4 pa[4], pb[4];
        if (kc < 3) {
            int k0 = (kc + 1) * 32;
#pragma unroll
            for (int i = 0; i < 4; i++) {
                int r = ldRow + 32 * i;
                pa[i] = *(const float4*)(A + (rowBase + r) * 128 + k0 + ldK);
                pb[i] = *(const float4*)(W + (colBase + r) * 128 + k0 + ldK);
            }
        }
        const float* Ac = As + (kc & 1) * GBUF;
        const float* Bc = Bs + (kc & 1) * GBUF;
#pragma unroll
        for (int ks = 0; ks < 4; ks++) {
            const int kb = ks * 8;
            uint32_t af[4][4], bf[4][2];
#pragma unroll
            for (int mf = 0; mf < 4; mf++) {
                int r0 = wm + mf * 16 + lr;
                af[mf][0] = ((const uint32_t*)Ac)[r0 * GP + kb + lc];
                af[mf][1] = ((const uint32_t*)Ac)[(r0 + 8) * GP + kb + lc];
                af[mf][2] = ((const uint32_t*)Ac)[r0 * GP + kb + 4 + lc];
                af[mf][3] = ((const uint32_t*)Ac)[(r0 + 8) * GP + kb + 4 + lc];
            }
#pragma unroll
            for (int nf = 0; nf < 4; nf++) {
                int c0 = wn + nf * 8 + lr;
                bf[nf][0] = ((const uint32_t*)Bc)[c0 * GP + kb + lc];
                bf[nf][1] = ((const uint32_t*)Bc)[c0 * GP + kb + 4 + lc];
            }
#pragma unroll
            for (int mf = 0; mf < 4; mf++)
#pragma unroll
                for (int nf = 0; nf < 4; nf++)
                    mma_tf32(acc[mf][nf], af[mf], bf[nf]);
        }
        if (kc < 3) {
            __syncthreads();
            float* Ad = As + ((kc + 1) & 1) * GBUF;
            float* Bd = Bs + ((kc + 1) & 1) * GBUF;
#pragma unroll
            for (int i = 0; i < 4; i++) {
                int r = ldRow + 32 * i;
                float* ap = Ad + r * GP + ldK;
                float* bp = Bd + r * GP + ldK;
                ((uint32_t*)ap)[0] = f2tf32(pa[i].x); ((uint32_t*)ap)[1] = f2tf32(pa[i].y);
                ((uint32_t*)ap)[2] = f2tf32(pa[i].z); ((uint32_t*)ap)[3] = f2tf32(pa[i].w);
                ((uint32_t*)bp)[0] = f2tf32(pb[i].x); ((uint32_t*)bp)[1] = f2tf32(pb[i].y);
                ((uint32_t*)bp)[2] = f2tf32(pb[i].z); ((uint32_t*)bp)[3] = f2tf32(pb[i].w);
            }
            __syncthreads();
        }
    }

#pragma unroll
    for (int nf = 0; nf < 4; nf++) {
        int c0 = colBase + wn + nf * 8 + 2 * lc;
        float b0 = Bb[c0], b1 = Bb[c0 + 1];
#pragma unroll
        for (int mf = 0; mf < 4; mf++) {
            int r0 = rowBase + wm + mf * 16 + lr;
            float2 o0, o1;
            o0.x = acc[mf][nf][0] + b0; o0.y = acc[mf][nf][1] + b1;
            o1.x = acc[mf][nf][2] + b0; o1.y = acc[mf][nf][3] + b1;
            *(float2*)(C + r0 * Ncols + c0) = o0;
            *(float2*)(C + (r0 + 8) * Ncols + c0) = o1;
        }
    }
}

// ------------------------- k_node -------------------------
__global__ void k_node(const float* __restrict__ h1, const float* __restrict__ h2,
                       const float* __restrict__ h3, const float* __restrict__ c1,
                       const float* __restrict__ c2, const float* __restrict__ c3,
                       const float* __restrict__ del_t, const float* __restrict__ dptr) {
    int j = (blockIdx.x * blockDim.x + threadIdx.x) >> 5;
    int ln = threadIdx.x & 31;
    if (j >= NN) return;
    const int off = j * HH;

    float s[4], m[4], t[4], ht[4];
    float accP[4] = {0, 0, 0, 0}, accS[4] = {0, 0, 0, 0}, accE[4] = {0, 0, 0, 0};
    float sdP = 0.f, sdS = 0.f;
    float4 scl;

    vld<4>(s, g_A1 + off, ln); expmap0<4, -1>(s); sigv<4>(s); logmap0<4, -1>(s);
    vld<4>(m, h1 + off, ln);
    pwmul<4, -1>(s, m, ht);
    { float lam = 2.f / (1.f - rawsq<4>(ht)); for (int i = 0; i < 4; i++) accP[i] += lam * ht[i]; sdP += lam - 1.f; }
    vcp<4>(t, ht); logmap0<4, -1>(t);
    for (int i = 0; i < 4; i++) accE[i] += t[i];
    vcp<4>(t, m); logmap0<4, -1>(t); expmap0<4, 1>(t);
    pwmul<4, -1>(s, t, ht);
    { float lam = 2.f / (1.f - rawsq<4>(ht)); for (int i = 0; i < 4; i++) accS[i] += lam * ht[i]; sdS += lam - 1.f; }

    vld<4>(s, g_A2 + off, ln); expmap0<4, 1>(s); sigv<4>(s); logmap0<4, 1>(s);
    vld<4>(m, h2 + off, ln);
    pwmul<4, 1>(s, m, ht);
    { float lam = 2.f / (1.f - rawsq<4>(ht)); for (int i = 0; i < 4; i++) accS[i] += lam * ht[i]; sdS += lam - 1.f; }
    vcp<4>(t, ht); logmap0<4, 1>(t);
    for (int i = 0; i < 4; i++) accE[i] += t[i];
    vcp<4>(t, m); logmap0<4, 1>(t); expmap0<4, -1>(t);
    pwmul<4, -1>(s, t, ht);
    { float lam = 2.f / (1.f - rawsq<4>(ht)); for (int i = 0; i < 4; i++) accP[i] += lam * ht[i]; sdP += lam - 1.f; }

    vld<4>(s, g_A3 + off, ln); sigv<4>(s);
    vld<4>(m, h3 + off, ln);
    for (int i = 0; i < 4; i++) accE[i] += s[i] * m[i];
    vcp<4>(t, m); expmap0<4, -1>(t); pwmul<4, -1>(s, t, ht);
    { float lam = 2.f / (1.f - rawsq<4>(ht)); for (int i = 0; i < 4; i++) accP[i] += lam * ht[i]; sdP += lam - 1.f; }
    vcp<4>(t, m); expmap0<4, 1>(t); pwmul<4, 1>(s, t, ht);
    { float lam = 2.f / (1.f - rawsq<4>(ht)); for (int i = 0; i < 4; i++) accS[i] += lam * ht[i]; sdS += lam - 1.f; }

    {
        float id = 1.f / fmaxf(fabsf(sdP), DEPS);
        for (int i = 0; i < 4; i++) ht[i] = accP[i] * id;
        smul_half<4, -1>(ht);
        for (int i = 0; i < 4; i++) ht[i] *= 3.f;
        vst<4>(g_H1P + off, ht, ln); scl.x = rawsq<4>(ht);
    }
    {
        float id = 1.f / fmaxf(fabsf(sdS), DEPS);
        for (int i = 0; i < 4; i++) ht[i] = accS[i] * id;
        smul_half<4, -1>(ht);
        for (int i = 0; i < 4; i++) ht[i] *= 3.f;
        vst<4>(g_H1S + off, ht, ln); scl.y = rawsq<4>(ht);
    }
    vst<4>(g_H1E + off, accE, ln);

    float g = dptr[0] / (del_t[j] + 1.f);

    {
        float csk[4], ckt[4], f[4], neg[4], t2[4];
        vld<4>(csk, g_C1 + off, ln);
        expmap0<4, -1>(csk); logmap0<4, -1>(csk); tanhv<4>(csk); expmap0<4, -1>(csk);
        vld<4>(m, c1 + off, ln);
        pwmul_scalar_x<4, -1>(csk, g, t);
        for (int i = 0; i < 4; i++) neg[i] = -csk[i];
        madd<4, -1>(neg, m, t2);
        madd<4, -1>(t2, t, ckt);
        vld<4>(f, g_F1 + off, ln); expmap0<4, -1>(f); logmap0<4, -1>(f); sigv<4>(f);
        pwmul<4, -1>(f, ckt, t);
        vst<4>(g_P1 + off, t, ln); scl.z = rawsq<4>(t);
    }
    {
        float csk[4], ckt[4], f[4], neg[4], t2[4];
        vld<4>(csk, g_C2 + off, ln);
        expmap0<4, 1>(csk); logmap0<4, 1>(csk); tanhv<4>(csk); expmap0<4, 1>(csk);
        vld<4>(m, c2 + off, ln);
        pwmul_scalar_x<4, 1>(csk, g, t);
        for (int i = 0; i < 4; i++) neg[i] = -csk[i];
        madd<4, 1>(neg, m, t2);
        madd<4, 1>(t2, t, ckt);
        vld<4>(f, g_F2 + off, ln); expmap0<4, 1>(f); logmap0<4, 1>(f); sigv<4>(f);
        pwmul<4, 1>(f, ckt, t);
        vst<4>(g_P2 + off, t, ln); scl.w = rawsq<4>(t);
    }
    {
        float csk[4], f[4];
        vld<4>(csk, g_C3 + off, ln); tanhv<4>(csk);
        vld<4>(m, c3 + off, ln);
        vld<4>(f, g_F3 + off, ln); sigv<4>(f);
        for (int i = 0; i < 4; i++) t[i] = f[i] * (m[i] - csk[i] + csk[i] * g);
        vst<4>(g_E3 + off, t, ln);
    }
    if (ln == 0) g_SCL[j] = scl;

    float2 qs;
    vld<4>(t, g_Q1 + off, ln); expmap0<4, -1>(t); vst<4>(g_XP + off, t, ln); qs.x = rawsq<4>(t);
    vld<4>(t, g_Q2 + off, ln); expmap0<4, 1>(t);  vst<4>(g_XS + off, t, ln); qs.y = rawsq<4>(t);
    if (ln == 0) g_QS[j] = qs;
}

// ------------------------- k_score -------------------------
__global__ void k_score(const int* __restrict__ nbr) {
    int p = blockIdx.x * 8 + (threadIdx.x >> 5);
    int ln = threadIdx.x & 31;
    if (p >= NN * 8) return;
    int n = p >> 3;
    int j = nbr[p];
    float2 q2 = g_QS[n];
    float4 scl = g_SCL[j];
    float q[4], v[4];

    vld<4>(q, g_XP + n * HH, ln);
    vld<4>(v, g_H1P + j * HH, ln);
    float qd = vdot<4>(q, v);
    float scp = -2.f * artanh_c(distnorm(q2.x, scl.x, qd, -1.f, true));

    vld<4>(q, g_XS + n * HH, ln);
    vld<4>(v, g_H1S + j * HH, ln);
    qd = vdot<4>(q, v);
    float scs = -2.f * atanf(distnorm(q2.y, scl.y, qd, 1.f, false));

    vld<4>(q, g_Q3 + n * HH, ln);
    vld<4>(v, g_H1E + j * HH, ln);
    float sce = vdot<4>(q, v) * 0.088388347648318447f;

    if (ln == 0) { g_SCP[p] = scp; g_SCS[p] = scs; g_SCE[p] = sce; }
}

// ------------------------- k_attn2: softmax + weighted wmid + cell-path sums (merged) ----
__global__ void k_attn2(const int* __restrict__ nbr) {
    int n = (blockIdx.x * blockDim.x + threadIdx.x) >> 5;
    int ln = threadIdx.x & 31;
    if (n >= NN) return;
    const int off = n * HH;

    float scp[8], scs[8], sce[8];
#pragma unroll
    for (int k = 0; k < 8; k++) {
        scp[k] = g_SCP[n * 8 + k];
        scs[k] = g_SCS[n * 8 + k];
        sce[k] = g_SCE[n * 8 + k];
    }
    softmax8(scp); softmax8(scs); softmax8(sce);

    float aP[4] = {0, 0, 0, 0}, aS[4] = {0, 0, 0, 0}, aE[4] = {0, 0, 0, 0};
    float aC1[4] = {0, 0, 0, 0}, aC2[4] = {0, 0, 0, 0}, aC3[4] = {0, 0, 0, 0};
    float sdp = 0.f, sds = 0.f, sd1 = 0.f, sd2 = 0.f;
#pragma unroll
    for (int k = 0; k < 8; k++) {
        int j = nbr[n * 8 + k];
        float4 scl = g_SCL[j];
        float v[4];
        vld<4>(v, g_H1P + j * HH, ln);
        { float lam = 2.f / (1.f - scl.x); float w = scp[k]; for (int i = 0; i < 4; i++) aP[i] += w * lam * v[i]; sdp += w * (lam - 1.f); }
        vld<4>(v, g_H1S + j * HH, ln);
        { float lam = 2.f / (1.f + scl.y); float w = scs[k]; for (int i = 0; i < 4; i++) aS[i] += w * lam * v[i]; sds += w * (lam - 1.f); }
        vld<4>(v, g_H1E + j * HH, ln);
        for (int i = 0; i < 4; i++) aE[i] += sce[k] * v[i];
        vld<4>(v, g_P1 + j * HH, ln);
        { float lam = 2.f / (1.f - scl.z); for (int i = 0; i < 4; i++) aC1[i] += lam * v[i]; sd1 += lam - 1.f; }
        vld<4>(v, g_P2 + j * HH, ln);
        { float lam = 2.f / (1.f + scl.w); for (int i = 0; i < 4; i++) aC2[i] += lam * v[i]; sd2 += lam - 1.f; }
        vld<4>(v, g_E3 + j * HH, ln);
        for (int i = 0; i < 4; i++) aC3[i] += v[i];
    }
    {
        float id = 1.f / fmaxf(fabsf(sdp), DEPS);
        float t[4];
        for (int i = 0; i < 4; i++) t[i] = aP[i] * id;
        smul_half<4, -1>(t);
        logmap0<4, -1>(t);
        vst<4>(g_lhtp + off, t, ln);
    }
    {
        float id = 1.f / fmaxf(fabsf(sds), DEPS);
        float t[4];
        for (int i = 0; i < 4; i++) t[i] = aS[i] * id;
        smul_half<4, 1>(t);
        logmap0<4, 1>(t);
        vst<4>(g_lhts + off, t, ln);
    }
    vst<4>(g_hte + off, aE, ln);
    {
        float id = 1.f / fmaxf(fabsf(sd1), DEPS);
        float t[4];
        for (int i = 0; i < 4; i++) t[i] = aC1[i] * id;
        smul_half<4, -1>(t);
        vst<4>(g_c1v + off, t, ln);
    }
    {
        float id = 1.f / fmaxf(fabsf(sd2), DEPS);
        float t[4];
        for (int i = 0; i < 4; i++) t[i] = aC2[i] * id;
        smul_half<4, 1>(t);
        vst<4>(g_c2v + off, t, ln);
    }
    vst<4>(g_c3v + off, aC3, ln);
}

// ------------------------- k_final -------------------------
__global__ void k_final(const float* __restrict__ iou1, const float* __restrict__ iou2,
                        const float* __restrict__ iou3, float* __restrict__ out) {
    int n = (blockIdx.x * blockDim.x + threadIdx.x) >> 5;
    int ln = threadIdx.x & 31;
    if (n >= NN) return;

    float gg[12], io[12], nio[12];
    float ip[4], op[4], up[4], piu[4], cc[4], nc[4], tt[4], nh[4];

    vld<12>(gg, g_G1 + n * IOU, ln);
    vld<12>(io, iou1 + n * IOU, ln);
    expmap0<12, -1>(gg);
    madd<12, -1>(io, gg, nio);
    for (int i = 0; i < 4; i++) { ip[i] = nio[i]; op[i] = nio[4 + i]; up[i] = nio[8 + i]; }
    logmap0<4, -1>(ip); sigv<4>(ip);
    logmap0<4, -1>(op); sigv<4>(op);
    logmap0<4, -1>(up); tanhv<4>(up);
    pwmul<4, -1>(ip, up, piu);
    vld<4>(cc, g_c1v + n * HH, ln);
    madd<4, -1>(piu, cc, nc);
    vst<4>(out + (1 * NN + n) * HH, nc, ln);
    vcp<4>(tt, nc); logmap0<4, -1>(tt); tanhv<4>(tt);
    pwmul<4, -1>(op, tt, nh);
    vst<4>(out + (0 * NN + n) * HH, nh, ln);

    vld<12>(gg, g_G2 + n * IOU, ln);
    vld<12>(io, iou2 + n * IOU, ln);
    expmap0<12, 1>(gg);
    madd<12, 1>(io, gg, nio);
    for (int i = 0; i < 4; i++) { ip[i] = nio[i]; op[i] = nio[4 + i]; up[i] = nio[8 + i]; }
    logmap0<4, 1>(ip); sigv<4>(ip);
    logmap0<4, 1>(op); sigv<4>(op);
    logmap0<4, 1>(up); tanhv<4>(up);
    pwmul<4, 1>(ip, up, piu);
    vld<4>(cc, g_c2v + n * HH, ln);
    madd<4, 1>(piu, cc, nc);
    vst<4>(out + (3 * NN + n) * HH, nc, ln);
    vcp<4>(tt, nc); logmap0<4, 1>(tt); tanhv<4>(tt);
    pwmul<4, 1>(op, tt, nh);
    vst<4>(out + (2 * NN + n) * HH, nh, ln);

    vld<12>(gg, g_G3 + n * IOU, ln);
    vld<12>(io, iou3 + n * IOU, ln);
    for (int i = 0; i < 12; i++) nio[i] = io[i] + gg[i];
    for (int i = 0; i < 4; i++) { ip[i] = nio[i]; op[i] = nio[4 + i]; up[i] = nio[8 + i]; }
    sigv<4>(ip); sigv<4>(op); tanhv<4>(up);
    vld<4>(cc, g_c3v + n * HH, ln);
    for (int i = 0; i < 4; i++) nc[i] = ip[i] * up[i] + cc[i];
    vst<4>(out + (5 * NN + n) * HH, nc, ln);
    for (int i = 0; i < 4; i++) nh[i] = op[i] * ftanh(nc[i]);
    vst<4>(out + (4 * NN + n) * HH, nh, ln);
}

// ------------------------- host -------------------------
extern "C" void kernel_launch(void* const* d_in, const int* in_sizes, int n_in,
                              void* d_out, int out_size) {
    const float* x     = (const float*)d_in[0];
    const float* h1    = (const float*)d_in[1];
    const float* c1    = (const float*)d_in[2];
    const float* h2    = (const float*)d_in[3];
    const float* c2    = (const float*)d_in[4];
    const float* h3    = (const float*)d_in[5];
    const float* c3    = (const float*)d_in[6];
    const float* del_t = (const float*)d_in[7];
    const float* iou1  = (const float*)d_in[8];
    const float* iou2  = (const float*)d_in[9];
    const float* iou3  = (const float*)d_in[10];
    const float* Wq_w  = (const float*)d_in[11];
    const float* Wq_b  = (const float*)d_in[12];
    const float* Wc_w  = (const float*)d_in[13];
    const float* Wc_b  = (const float*)d_in[14];
    const float* Uf_w  = (const float*)d_in[15];
    const float* Uf_b  = (const float*)d_in[16];
    const float* Up_w  = (const float*)d_in[17];
    const float* Up_b  = (const float*)d_in[18];
    const float* Uiou_w = (const float*)d_in[19];
    const float* Uiou_b = (const float*)d_in[20];
    const float* dptr  = (const float*)d_in[21];
    const int*   nbr   = (const int*)d_in[22];
    float* out = (float*)d_out;
    (void)in_sizes; (void)n_in; (void)out_size;

    float *pL1, *pL2, *pLc1, *pLc2, *plxp, *plxs;
    float *pA1, *pA2, *pA3, *pF1, *pF2, *pF3, *pC1, *pC2, *pC3, *pQ1, *pQ2, *pQ3;
    float *plhtp, *plhts, *phte, *pG1, *pG2, *pG3;
    cudaGetSymbolAddress((void**)&pL1, g_L1);
    cudaGetSymbolAddress((void**)&pL2, g_L2);
    cudaGetSymbolAddress((void**)&pLc1, g_Lc1);
    cudaGetSymbolAddress((void**)&pLc2, g_Lc2);
    cudaGetSymbolAddress((void**)&plxp, g_lxp);
    cudaGetSymbolAddress((void**)&plxs, g_lxs);
    cudaGetSymbolAddress((void**)&pA1, g_A1);
    cudaGetSymbolAddress((void**)&pA2, g_A2);
    cudaGetSymbolAddress((void**)&pA3, g_A3);
    cudaGetSymbolAddress((void**)&pF1, g_F1);
    cudaGetSymbolAddress((void**)&pF2, g_F2);
    cudaGetSymbolAddress((void**)&pF3, g_F3);
    cudaGetSymbolAddress((void**)&pC1, g_C1);
    cudaGetSymbolAddress((void**)&pC2, g_C2);
    cudaGetSymbolAddress((void**)&pC3, g_C3);
    cudaGetSymbolAddress((void**)&pQ1, g_Q1);
    cudaGetSymbolAddress((void**)&pQ2, g_Q2);
    cudaGetSymbolAddress((void**)&pQ3, g_Q3);
    cudaGetSymbolAddress((void**)&plhtp, g_lhtp);
    cudaGetSymbolAddress((void**)&plhts, g_lhts);
    cudaGetSymbolAddress((void**)&phte, g_hte);
    cudaGetSymbolAddress((void**)&pG1, g_G1);
    cudaGetSymbolAddress((void**)&pG2, g_G2);
    cudaGetSymbolAddress((void**)&pG3, g_G3);

    const int GEMM_SMEM = 4 * GBUF * (int)sizeof(float);
    static int smem_set = 0;
    if (!smem_set) {
        cudaFuncSetAttribute(gemm_tf32, cudaFuncAttributeMaxDynamicSharedMemorySize, GEMM_SMEM);
        smem_set = 1;
    }

    k_prep<<<1024, 256>>>(x, h1, h2, c1, c2);

    GemmJobs jA;
    const float* inA[12] = {pL1, pL2, h3, pL1, pL2, h3, pLc1, pLc2, c3, plxp, plxs, x};
    const float* wA[12]  = {Up_w, Up_w, Up_w, Uf_w, Uf_w, Uf_w, Wc_w, Wc_w, Wc_w, Wq_w, Wq_w, Wq_w};
    const float* bA[12]  = {Up_b, Up_b, Up_b, Uf_b, Uf_b, Uf_b, Wc_b, Wc_b, Wc_b, Wq_b, Wq_b, Wq_b};
    float* cA[12]        = {pA1, pA2, pA3, pF1, pF2, pF3, pC1, pC2, pC3, pQ1, pQ2, pQ3};
    for (int i = 0; i < 12; i++) { jA.A[i] = inA[i]; jA.W[i] = wA[i]; jA.B[i] = bA[i]; jA.C[i] = cA[i]; }
    gemm_tf32<<<dim3(64, 1, 12), 256, GEMM_SMEM>>>(jA, 128);

    k_node<<<1024, 256>>>(h1, h2, h3, c1, c2, c3, del_t, dptr);
    k_score<<<8192, 256>>>(nbr);
    k_attn2<<<1024, 256>>>(nbr);

    GemmJobs jC;
    for (int i = 0; i < 12; i++) { jC.A[i] = plhtp; jC.W[i] = Uiou_w; jC.B[i] = Uiou_b; jC.C[i] = pG1; }
    jC.A[0] = plhtp; jC.C[0] = pG1;
    jC.A[1] = plhts; jC.C[1] = pG2;
    jC.A[2] = phte;  jC.C[2] = pG3;
    gemm_tf32<<<dim3(64, 3, 3), 256, GEMM_SMEM>>>(jC, IOU);

    k_final<<<1024, 256>>>(iou1, iou2, iou3, out);
}

// round 15
// speedup vs baseline: 1.6273x; 1.6273x over previous
#include <cuda_runtime.h>
#include <math.h>
#include <stdint.h>

#define NN 8192
#define HH 128
#define IOU 384
#define DEPS 1e-6f
#define DINL __device__ __forceinline__

// ------------------------- device scratch (no cudaMalloc allowed) -------------------------
__device__ float g_L1[NN*HH], g_L2[NN*HH], g_Lc1[NN*HH], g_Lc2[NN*HH], g_lxp[NN*HH], g_lxs[NN*HH];
__device__ float g_A1[NN*HH], g_A2[NN*HH], g_A3[NN*HH];
__device__ float g_F1[NN*HH], g_F2[NN*HH], g_F3[NN*HH];
__device__ float g_C1[NN*HH], g_C2[NN*HH], g_C3[NN*HH];
__device__ float g_Q1[NN*HH], g_Q2[NN*HH], g_Q3[NN*HH];
__device__ float g_H1P[NN*HH], g_H1S[NN*HH], g_H1E[NN*HH];
__device__ float g_P1[NN*HH], g_P2[NN*HH], g_E3[NN*HH];
__device__ float g_XP[NN*HH], g_XS[NN*HH];
__device__ float4 g_SCL[NN];
__device__ float2 g_QS[NN];
__device__ float g_SCP[NN*8], g_SCS[NN*8], g_SCE[NN*8];
__device__ float g_lhtp[NN*HH], g_lhts[NN*HH], g_hte[NN*HH];
__device__ float g_c1v[NN*HH], g_c2v[NN*HH], g_c3v[NN*HH];
__device__ float g_G1[NN*IOU], g_G2[NN*IOU], g_G3[NN*IOU];

// ------------------------- fast scalar math (MUFU-based) -------------------------
DINL float fdiv(float a, float b) { return __fdividef(a, b); }
DINL float ftanh(float x) {                 // overflow-safe, ~1e-6 rel err
    float a = fabsf(x);
    float e = __expf(2.f * a);              // inf for large a -> t = 1
    float t = 1.f - fdiv(2.f, e + 1.f);
    return copysignf(t, x);
}
DINL float fsig(float x) { return fdiv(1.f, 1.f + __expf(-x)); }

// ------------------------- warp-distributed vector helpers -------------------------
DINL float wsum(float v) {
#pragma unroll
    for (int o = 16; o; o >>= 1) v += __shfl_xor_sync(0xffffffffu, v, o);
    return v;
}
template<int D> DINL void vld(float* v, const float* p, int ln) {
#pragma unroll
    for (int i = 0; i < D; i++) v[i] = p[ln + 32 * i];
}
template<int D> DINL void vst(float* p, const float* v, int ln) {
#pragma unroll
    for (int i = 0; i < D; i++) p[ln + 32 * i] = v[i];
}
template<int D> DINL float rawsq(const float* v) {
    float s = 0.f;
#pragma unroll
    for (int i = 0; i < D; i++) s += v[i] * v[i];
    return wsum(s);
}
template<int D> DINL float vnorm(const float* v) { return sqrtf(rawsq<D>(v) + 1e-15f); }
template<int D> DINL float vdot(const float* a, const float* b) {
    float s = 0.f;
#pragma unroll
    for (int i = 0; i < D; i++) s += a[i] * b[i];
    return wsum(s);
}

DINL float artanh_c(float u) {
    u = fminf(fmaxf(u, -0.99999f), 0.99999f);
    return 0.5f * __logf(fdiv(1.f + u, 1.f - u));
}
DINL float tan_c(float u) { return __tanf(fminf(fmaxf(u, -1.47079f), 1.47079f)); }
template<int S> DINL float artank(float u) { return (S < 0) ? artanh_c(u) : atanf(u); }
template<int S> DINL float tank(float u)   { return (S < 0) ? ftanh(u)    : tan_c(u); }

template<int D, int S> DINL void projk(float* v) {
    if (S < 0) {
        float n = vnorm<D>(v);
        if (n > 0.9999f) {
            float s = fdiv(0.9999f, n);
#pragma unroll
            for (int i = 0; i < D; i++) v[i] *= s;
        }
    }
}
template<int D, int S> DINL void logmap0(float* v) {
    float n = vnorm<D>(v);
    float s = fdiv(artank<S>(n), n);
#pragma unroll
    for (int i = 0; i < D; i++) v[i] *= s;
}
template<int D, int S> DINL void expmap0(float* v) {
    float n = vnorm<D>(v);
    float s = fdiv(tank<S>(n), n);
#pragma unroll
    for (int i = 0; i < D; i++) v[i] *= s;
    projk<D, S>(v);
}
template<int D, int S> DINL void smul_half(float* v) {
    float n = vnorm<D>(v);
    float s = fdiv(tank<S>(0.5f * artank<S>(n)), n);
#pragma unroll
    for (int i = 0; i < D; i++) v[i] *= s;
    projk<D, S>(v);
}
template<int D, int S> DINL void pwmul(const float* w, const float* x, float* out) {
    float wx[D];
#pragma unroll
    for (int i = 0; i < D; i++) wx[i] = w[i] * x[i];
    float nx = vnorm<D>(x), nwx = vnorm<D>(wx);
    float s = fdiv(tank<S>(fdiv(nwx, nx) * artank<S>(nx)), nwx);
#pragma unroll
    for (int i = 0; i < D; i++) out[i] = s * wx[i];
    projk<D, S>(out);
}
template<int D, int S> DINL void pwmul_scalar_x(const float* csk, float g, float* out) {
    float rn2 = rawsq<D>(csk);
    float nx  = sqrtf(g * g + 1e-15f);
    float nwx = sqrtf(g * g * rn2 + 1e-15f);
    float sc  = fdiv(tank<S>(fdiv(nwx, nx) * artank<S>(nx)), nwx) * g;
#pragma unroll
    for (int i = 0; i < D; i++) out[i] = sc * csk[i];
    projk<D, S>(out);
}
DINL float safeden(float d) { return d >= 0.f ? fmaxf(d, DEPS) : fminf(d, -DEPS); }
template<int D, int S> DINL void madd(const float* x, const float* y, float* out) {
    float sx = 0.f, sy = 0.f, sxy = 0.f;
#pragma unroll
    for (int i = 0; i < D; i++) { sx += x[i] * x[i]; sy += y[i] * y[i]; sxy += x[i] * y[i]; }
    sx = wsum(sx); sy = wsum(sy); sxy = wsum(sxy);
    const float k = (float)S;
    float a = 1.f - 2.f * k * sxy - k * sy;
    float b = 1.f + k * sx;
    float id = fdiv(1.f, safeden(1.f - 2.f * k * sxy + sx * sy));
#pragma unroll
    for (int i = 0; i < D; i++) out[i] = (a * x[i] + b * y[i]) * id;
    projk<D, S>(out);
}
template<int D> DINL void sigv(float* v) {
#pragma unroll
    for (int i = 0; i < D; i++) v[i] = fsig(v[i]);
}
template<int D> DINL void tanhv(float* v) {
#pragma unroll
    for (int i = 0; i < D; i++) v[i] = ftanh(v[i]);
}
template<int D> DINL void vcp(float* d, const float* s) {
#pragma unroll
    for (int i = 0; i < D; i++) d[i] = s[i];
}

DINL float distnorm(float x2, float y2, float qd, float k, bool clipP) {
    float A = 1.f + 2.f * k * qd - k * y2;
    float B = 1.f + k * x2;
    float den = safeden(1.f + 2.f * k * qd + x2 * y2);
    float num2 = fmaxf(A * A * x2 + B * B * y2 - 2.f * A * B * qd, 0.f);
    float nz = sqrtf(fdiv(num2, den * den) + 1e-15f);
    if (clipP) nz = fminf(nz, 0.9999f);
    return nz;
}
DINL void softmax8(float* s) {
    float m = s[0];
#pragma unroll
    for (int k = 1; k < 8; k++) m = fmaxf(m, s[k]);
    float t = 0.f;
#pragma unroll
    for (int k = 0; k < 8; k++) { s[k] = __expf(s[k] - m); t += s[k]; }
    float it = fdiv(1.f, t);
#pragma unroll
    for (int k = 0; k < 8; k++) s[k] *= it;
}

// ------------------------- k_prep -------------------------
__global__ void k_prep(const float* __restrict__ x, const float* __restrict__ h1,
                       const float* __restrict__ h2, const float* __restrict__ c1,
                       const float* __restrict__ c2) {
    int w = (blockIdx.x * blockDim.x + threadIdx.x) >> 5;
    int ln = threadIdx.x & 31;
    if (w >= NN) return;
    const int off = w * HH;
    float v[4];
    vld<4>(v, h1 + off, ln); logmap0<4, -1>(v); vst<4>(g_L1 + off, v, ln);
    vld<4>(v, h2 + off, ln); logmap0<4, 1>(v);  vst<4>(g_L2 + off, v, ln);
    vld<4>(v, c1 + off, ln); logmap0<4, -1>(v); vst<4>(g_Lc1 + off, v, ln);
    vld<4>(v, c2 + off, ln); logmap0<4, 1>(v);  vst<4>(g_Lc2 + off, v, ln);
    vld<4>(v, x + off, ln);  expmap0<4, -1>(v); logmap0<4, -1>(v); vst<4>(g_lxp + off, v, ln);
    vld<4>(v, x + off, ln);  expmap0<4, 1>(v);  logmap0<4, 1>(v);  vst<4>(g_lxs + off, v, ln);
}

// ------------------------- tf32 tensor-core batched GEMM -------------------------
struct GemmJobs {
    const float* A[12];
    const float* W[12];
    const float* B[12];
    float* C[12];
};

#define GP 36
#define GBUF (128 * GP)

DINL uint32_t f2tf32(float f) {
    uint32_t o;
    asm("cvt.rna.tf32.f32 %0, %1;" : "=r"(o) : "f"(f));
    return o;
}
DINL void mma_tf32(float* c, const uint32_t* a, const uint32_t* b) {
    asm volatile(
        "mma.sync.aligned.m16n8k8.row.col.f32.tf32.tf32.f32 "
        "{%0,%1,%2,%3}, {%4,%5,%6,%7}, {%8,%9}, {%0,%1,%2,%3};"
        : "+f"(c[0]), "+f"(c[1]), "+f"(c[2]), "+f"(c[3])
        : "r"(a[0]), "r"(a[1]), "r"(a[2]), "r"(a[3]), "r"(b[0]), "r"(b[1]));
}

__global__ __launch_bounds__(256) void gemm_tf32(GemmJobs J, int Ncols) {
    extern __shared__ float sm[];
    float* As = sm;
    float* Bs = sm + 2 * GBUF;

    const int jb = blockIdx.z;
    const float* __restrict__ A = J.A[jb];
    const float* __restrict__ W = J.W[jb];
    const float* __restrict__ Bb = J.B[jb];
    float* __restrict__ C = J.C[jb];
    const int rowBase = blockIdx.x * 128;
    const int colBase = blockIdx.y * 128;

    const int tid = threadIdx.x, lane = tid & 31, warp = tid >> 5;
    const int wm = (warp & 1) * 64;
    const int wn = (warp >> 1) * 32;
    const int lr = lane >> 2;
    const int lc = lane & 3;

    const int ldRow = tid >> 3;
    const int ldK   = (tid & 7) * 4;

    float acc[4][4][4];
#pragma unroll
    for (int mf = 0; mf < 4; mf++)
#pragma unroll
        for (int nf = 0; nf < 4; nf++)
#pragma unroll
            for (int q = 0; q < 4; q++) acc[mf][nf][q] = 0.f;

    {
        float* Ad = As;
        float* Bd = Bs;
#pragma unroll
        for (int i = 0; i < 4; i++) {
            int r = ldRow + 32 * i;
            float4 av = *(const float4*)(A + (rowBase + r) * 128 + ldK);
            float4 bv = *(const float4*)(W + (colBase + r) * 128 + ldK);
            float* ap = Ad + r * GP + ldK;
            float* bp = Bd + r * GP + ldK;
            ((uint32_t*)ap)[0] = f2tf32(av.x); ((uint32_t*)ap)[1] = f2tf32(av.y);
            ((uint32_t*)ap)[2] = f2tf32(av.z); ((uint32_t*)ap)[3] = f2tf32(av.w);
            ((uint32_t*)bp)[0] = f2tf32(bv.x); ((uint32_t*)bp)[1] = f2tf32(bv.y);
            ((uint32_t*)bp)[2] = f2tf32(bv.z); ((uint32_t*)bp)[3] = f2tf32(bv.w);
        }
    }
    __syncthreads();

#pragma unroll
    for (int kc = 0; kc < 4; kc++) {
        float4 pa[4], pb[4];
        if (kc < 3) {
            int k0 = (kc + 1) * 32;
#pragma unroll
            for (int i = 0; i < 4; i++) {
                int r = ldRow + 32 * i;
                pa[i] = *(const float4*)(A + (rowBase + r) * 128 + k0 + ldK);
                pb[i] = *(const float4*)(W + (colBase + r) * 128 + k0 + ldK);
            }
        }
        const float* Ac = As + (kc & 1) * GBUF;
        const float* Bc = Bs + (kc & 1) * GBUF;
#pragma unroll
        for (int ks = 0; ks < 4; ks++) {
            const int kb = ks * 8;
            uint32_t af[4][4], bf[4][2];
#pragma unroll
            for (int mf = 0; mf < 4; mf++) {
                int r0 = wm + mf * 16 + lr;
                af[mf][0] = ((const uint32_t*)Ac)[r0 * GP + kb + lc];
                af[mf][1] = ((const uint32_t*)Ac)[(r0 + 8) * GP + kb + lc];
                af[mf][2] = ((const uint32_t*)Ac)[r0 * GP + kb + 4 + lc];
                af[mf][3] = ((const uint32_t*)Ac)[(r0 + 8) * GP + kb + 4 + lc];
            }
#pragma unroll
            for (int nf = 0; nf < 4; nf++) {
                int c0 = wn + nf * 8 + lr;
                bf[nf][0] = ((const uint32_t*)Bc)[c0 * GP + kb + lc];
                bf[nf][1] = ((const uint32_t*)Bc)[c0 * GP + kb + 4 + lc];
            }
#pragma unroll
            for (int mf = 0; mf < 4; mf++)
#pragma unroll
                for (int nf = 0; nf < 4; nf++)
                    mma_tf32(acc[mf][nf], af[mf], bf[nf]);
        }
        if (kc < 3) {
            __syncthreads();
            float* Ad = As + ((kc + 1) & 1) * GBUF;
            float* Bd = Bs + ((kc + 1) & 1) * GBUF;
#pragma unroll
            for (int i = 0; i < 4; i++) {
                int r = ldRow + 32 * i;
                float* ap = Ad + r * GP + ldK;
                float* bp = Bd + r * GP + ldK;
                ((uint32_t*)ap)[0] = f2tf32(pa[i].x); ((uint32_t*)ap)[1] = f2tf32(pa[i].y);
                ((uint32_t*)ap)[2] = f2tf32(pa[i].z); ((uint32_t*)ap)[3] = f2tf32(pa[i].w);
                ((uint32_t*)bp)[0] = f2tf32(pb[i].x); ((uint32_t*)bp)[1] = f2tf32(pb[i].y);
                ((uint32_t*)bp)[2] = f2tf32(pb[i].z); ((uint32_t*)bp)[3] = f2tf32(pb[i].w);
            }
            __syncthreads();
        }
    }

#pragma unroll
    for (int nf = 0; nf < 4; nf++) {
        int c0 = colBase + wn + nf * 8 + 2 * lc;
        float b0 = Bb[c0], b1 = Bb[c0 + 1];
#pragma unroll
        for (int mf = 0; mf < 4; mf++) {
            int r0 = rowBase + wm + mf * 16 + lr;
            float2 o0, o1;
            o0.x = acc[mf][nf][0] + b0; o0.y = acc[mf][nf][1] + b1;
            o1.x = acc[mf][nf][2] + b0; o1.y = acc[mf][nf][3] + b1;
            *(float2*)(C + r0 * Ncols + c0) = o0;
            *(float2*)(C + (r0 + 8) * Ncols + c0) = o1;
        }
    }
}

// ------------------------- k_node -------------------------
__global__ void k_node(const float* __restrict__ h1, const float* __restrict__ h2,
                       const float* __restrict__ h3, const float* __restrict__ c1,
                       const float* __restrict__ c2, const float* __restrict__ c3,
                       const float* __restrict__ del_t, const float* __restrict__ dptr) {
    int j = (blockIdx.x * blockDim.x + threadIdx.x) >> 5;
    int ln = threadIdx.x & 31;
    if (j >= NN) return;
    const int off = j * HH;

    float s[4], m[4], t[4], ht[4];
    float accP[4] = {0, 0, 0, 0}, accS[4] = {0, 0, 0, 0}, accE[4] = {0, 0, 0, 0};
    float sdP = 0.f, sdS = 0.f;
    float4 scl;

    vld<4>(s, g_A1 + off, ln); expmap0<4, -1>(s); sigv<4>(s); logmap0<4, -1>(s);
    vld<4>(m, h1 + off, ln);
    pwmul<4, -1>(s, m, ht);
    { float lam = fdiv(2.f, 1.f - rawsq<4>(ht)); for (int i = 0; i < 4; i++) accP[i] += lam * ht[i]; sdP += lam - 1.f; }
    vcp<4>(t, ht); logmap0<4, -1>(t);
    for (int i = 0; i < 4; i++) accE[i] += t[i];
    vcp<4>(t, m); logmap0<4, -1>(t); expmap0<4, 1>(t);
    pwmul<4, -1>(s, t, ht);
    { float lam = fdiv(2.f, 1.f - rawsq<4>(ht)); for (int i = 0; i < 4; i++) accS[i] += lam * ht[i]; sdS += lam - 1.f; }

    vld<4>(s, g_A2 + off, ln); expmap0<4, 1>(s); sigv<4>(s); logmap0<4, 1>(s);
    vld<4>(m, h2 + off, ln);
    pwmul<4, 1>(s, m, ht);
    { float lam = fdiv(2.f, 1.f - rawsq<4>(ht)); for (int i = 0; i < 4; i++) accS[i] += lam * ht[i]; sdS += lam - 1.f; }
    vcp<4>(t, ht); logmap0<4, 1>(t);
    for (int i = 0; i < 4; i++) accE[i] += t[i];
    vcp<4>(t, m); logmap0<4, 1>(t); expmap0<4, -1>(t);
    pwmul<4, -1>(s, t, ht);
    { float lam = fdiv(2.f, 1.f - rawsq<4>(ht)); for (int i = 0; i < 4; i++) accP[i] += lam * ht[i]; sdP += lam - 1.f; }

    vld<4>(s, g_A3 + off, ln); sigv<4>(s);
    vld<4>(m, h3 + off, ln);
    for (int i = 0; i < 4; i++) accE[i] += s[i] * m[i];
    vcp<4>(t, m); expmap0<4, -1>(t); pwmul<4, -1>(s, t, ht);
    { float lam = fdiv(2.f, 1.f - rawsq<4>(ht)); for (int i = 0; i < 4; i++) accP[i] += lam * ht[i]; sdP += lam - 1.f; }
    vcp<4>(t, m); expmap0<4, 1>(t); pwmul<4, 1>(s, t, ht);
    { float lam = fdiv(2.f, 1.f - rawsq<4>(ht)); for (int i = 0; i < 4; i++) accS[i] += lam * ht[i]; sdS += lam - 1.f; }

    {
        float id = fdiv(1.f, fmaxf(fabsf(sdP), DEPS));
        for (int i = 0; i < 4; i++) ht[i] = accP[i] * id;
        smul_half<4, -1>(ht);
        for (int i = 0; i < 4; i++) ht[i] *= 3.f;
        vst<4>(g_H1P + off, ht, ln); scl.x = rawsq<4>(ht);
    }
    {
        float id = fdiv(1.f, fmaxf(fabsf(sdS), DEPS));
        for (int i = 0; i < 4; i++) ht[i] = accS[i] * id;
        smul_half<4, -1>(ht);
        for (int i = 0; i < 4; i++) ht[i] *= 3.f;
        vst<4>(g_H1S + off, ht, ln); scl.y = rawsq<4>(ht);
    }
    vst<4>(g_H1E + off, accE, ln);

    float g = fdiv(dptr[0], del_t[j] + 1.f);

    {
        float csk[4], ckt[4], f[4], neg[4], t2[4];
        vld<4>(csk, g_C1 + off, ln);
        expmap0<4, -1>(csk); logmap0<4, -1>(csk); tanhv<4>(csk); expmap0<4, -1>(csk);
        vld<4>(m, c1 + off, ln);
        pwmul_scalar_x<4, -1>(csk, g, t);
        for (int i = 0; i < 4; i++) neg[i] = -csk[i];
        madd<4, -1>(neg, m, t2);
        madd<4, -1>(t2, t, ckt);
        vld<4>(f, g_F1 + off, ln); expmap0<4, -1>(f); logmap0<4, -1>(f); sigv<4>(f);
        pwmul<4, -1>(f, ckt, t);
        vst<4>(g_P1 + off, t, ln); scl.z = rawsq<4>(t);
    }
    {
        float csk[4], ckt[4], f[4], neg[4], t2[4];
        vld<4>(csk, g_C2 + off, ln);
        expmap0<4, 1>(csk); logmap0<4, 1>(csk); tanhv<4>(csk); expmap0<4, 1>(csk);
        vld<4>(m, c2 + off, ln);
        pwmul_scalar_x<4, 1>(csk, g, t);
        for (int i = 0; i < 4; i++) neg[i] = -csk[i];
        madd<4, 1>(neg, m, t2);
        madd<4, 1>(t2, t, ckt);
        vld<4>(f, g_F2 + off, ln); expmap0<4, 1>(f); logmap0<4, 1>(f); sigv<4>(f);
        pwmul<4, 1>(f, ckt, t);
        vst<4>(g_P2 + off, t, ln); scl.w = rawsq<4>(t);
    }
    {
        float csk[4], f[4];
        vld<4>(csk, g_C3 + off, ln); tanhv<4>(csk);
        vld<4>(m, c3 + off, ln);
        vld<4>(f, g_F3 + off, ln); sigv<4>(f);
        for (int i = 0; i < 4; i++) t[i] = f[i] * (m[i] - csk[i] + csk[i] * g);
        vst<4>(g_E3 + off, t, ln);
    }
    if (ln == 0) g_SCL[j] = scl;

    float2 qs;
    vld<4>(t, g_Q1 + off, ln); expmap0<4, -1>(t); vst<4>(g_XP + off, t, ln); qs.x = rawsq<4>(t);
    vld<4>(t, g_Q2 + off, ln); expmap0<4, 1>(t);  vst<4>(g_XS + off, t, ln); qs.y = rawsq<4>(t);
    if (ln == 0) g_QS[j] = qs;
}

// ------------------------- k_score -------------------------
__global__ void k_score(const int* __restrict__ nbr) {
    int p = blockIdx.x * 8 + (threadIdx.x >> 5);
    int ln = threadIdx.x & 31;
    if (p >= NN * 8) return;
    int n = p >> 3;
    int j = nbr[p];
    float2 q2 = g_QS[n];
    float4 scl = g_SCL[j];
    float q[4], v[4];

    vld<4>(q, g_XP + n * HH, ln);
    vld<4>(v, g_H1P + j * HH, ln);
    float qd = vdot<4>(q, v);
    float scp = -2.f * artanh_c(distnorm(q2.x, scl.x, qd, -1.f, true));

    vld<4>(q, g_XS + n * HH, ln);
    vld<4>(v, g_H1S + j * HH, ln);
    qd = vdot<4>(q, v);
    float scs = -2.f * atanf(distnorm(q2.y, scl.y, qd, 1.f, false));

    vld<4>(q, g_Q3 + n * HH, ln);
    vld<4>(v, g_H1E + j * HH, ln);
    float sce = vdot<4>(q, v) * 0.088388347648318447f;

    if (ln == 0) { g_SCP[p] = scp; g_SCS[p] = scs; g_SCE[p] = sce; }
}

// ------------------------- k_attn2: softmax + weighted wmid + cell-path sums (merged) ----
__global__ void k_attn2(const int* __restrict__ nbr) {
    int n = (blockIdx.x * blockDim.x + threadIdx.x) >> 5;
    int ln = threadIdx.x & 31;
    if (n >= NN) return;
    const int off = n * HH;

    float scp[8], scs[8], sce[8];
#pragma unroll
    for (int k = 0; k < 8; k++) {
        scp[k] = g_SCP[n * 8 + k];
        scs[k] = g_SCS[n * 8 + k];
        sce[k] = g_SCE[n * 8 + k];
    }
    softmax8(scp); softmax8(scs); softmax8(sce);

    float aP[4] = {0, 0, 0, 0}, aS[4] = {0, 0, 0, 0}, aE[4] = {0, 0, 0, 0};
    float aC1[4] = {0, 0, 0, 0}, aC2[4] = {0, 0, 0, 0}, aC3[4] = {0, 0, 0, 0};
    float sdp = 0.f, sds = 0.f, sd1 = 0.f, sd2 = 0.f;
#pragma unroll
    for (int k = 0; k < 8; k++) {
        int j = nbr[n * 8 + k];
        float4 scl = g_SCL[j];
        float v[4];
        vld<4>(v, g_H1P + j * HH, ln);
        { float lam = fdiv(2.f, 1.f - scl.x); float w = scp[k]; for (int i = 0; i < 4; i++) aP[i] += w * lam * v[i]; sdp += w * (lam - 1.f); }
        vld<4>(v, g_H1S + j * HH, ln);
        { float lam = fdiv(2.f, 1.f + scl.y); float w = scs[k]; for (int i = 0; i < 4; i++) aS[i] += w * lam * v[i]; sds += w * (lam - 1.f); }
        vld<4>(v, g_H1E + j * HH, ln);
        for (int i = 0; i < 4; i++) aE[i] += sce[k] * v[i];
        vld<4>(v, g_P1 + j * HH, ln);
        { float lam = fdiv(2.f, 1.f - scl.z); for (int i = 0; i < 4; i++) aC1[i] += lam * v[i]; sd1 += lam - 1.f; }
        vld<4>(v, g_P2 + j * HH, ln);
        { float lam = fdiv(2.f, 1.f + scl.w); for (int i = 0; i < 4; i++) aC2[i] += lam * v[i]; sd2 += lam - 1.f; }
        vld<4>(v, g_E3 + j * HH, ln);
        for (int i = 0; i < 4; i++) aC3[i] += v[i];
    }
    {
        float id = fdiv(1.f, fmaxf(fabsf(sdp), DEPS));
        float t[4];
        for (int i = 0; i < 4; i++) t[i] = aP[i] * id;
        smul_half<4, -1>(t);
        logmap0<4, -1>(t);
        vst<4>(g_lhtp + off, t, ln);
    }
    {
        float id = fdiv(1.f, fmaxf(fabsf(sds), DEPS));
        float t[4];
        for (int i = 0; i < 4; i++) t[i] = aS[i] * id;
        smul_half<4, 1>(t);
        logmap0<4, 1>(t);
        vst<4>(g_lhts + off, t, ln);
    }
    vst<4>(g_hte + off, aE, ln);
    {
        float id = fdiv(1.f, fmaxf(fabsf(sd1), DEPS));
        float t[4];
        for (int i = 0; i < 4; i++) t[i] = aC1[i] * id;
        smul_half<4, -1>(t);
        vst<4>(g_c1v + off, t, ln);
    }
    {
        float id = fdiv(1.f, fmaxf(fabsf(sd2), DEPS));
        float t[4];
        for (int i = 0; i < 4; i++) t[i] = aC2[i] * id;
        smul_half<4, 1>(t);
        vst<4>(g_c2v + off, t, ln);
    }
    vst<4>(g_c3v + off, aC3, ln);
}

// ------------------------- k_final -------------------------
__global__ void k_final(const float* __restrict__ iou1, const float* __restrict__ iou2,
                        const float* __restrict__ iou3, float* __restrict__ out) {
    int n = (blockIdx.x * blockDim.x + threadIdx.x) >> 5;
    int ln = threadIdx.x & 31;
    if (n >= NN) return;

    float gg[12], io[12], nio[12];
    float ip[4], op[4], up[4], piu[4], cc[4], nc[4], tt[4], nh[4];

    vld<12>(gg, g_G1 + n * IOU, ln);
    vld<12>(io, iou1 + n * IOU, ln);
    expmap0<12, -1>(gg);
    madd<12, -1>(io, gg, nio);
    for (int i = 0; i < 4; i++) { ip[i] = nio[i]; op[i] = nio[4 + i]; up[i] = nio[8 + i]; }
    logmap0<4, -1>(ip); sigv<4>(ip);
    logmap0<4, -1>(op); sigv<4>(op);
    logmap0<4, -1>(up); tanhv<4>(up);
    pwmul<4, -1>(ip, up, piu);
    vld<4>(cc, g_c1v + n * HH, ln);
    madd<4, -1>(piu, cc, nc);
    vst<4>(out + (1 * NN + n) * HH, nc, ln);
    vcp<4>(tt, nc); logmap0<4, -1>(tt); tanhv<4>(tt);
    pwmul<4, -1>(op, tt, nh);
    vst<4>(out + (0 * NN + n) * HH, nh, ln);

    vld<12>(gg, g_G2 + n * IOU, ln);
    vld<12>(io, iou2 + n * IOU, ln);
    expmap0<12, 1>(gg);
    madd<12, 1>(io, gg, nio);
    for (int i = 0; i < 4; i++) { ip[i] = nio[i]; op[i] = nio[4 + i]; up[i] = nio[8 + i]; }
    logmap0<4, 1>(ip); sigv<4>(ip);
    logmap0<4, 1>(op); sigv<4>(op);
    logmap0<4, 1>(up); tanhv<4>(up);
    pwmul<4, 1>(ip, up, piu);
    vld<4>(cc, g_c2v + n * HH, ln);
    madd<4, 1>(piu, cc, nc);
    vst<4>(out + (3 * NN + n) * HH, nc, ln);
    vcp<4>(tt, nc); logmap0<4, 1>(tt); tanhv<4>(tt);
    pwmul<4, 1>(op, tt, nh);
    vst<4>(out + (2 * NN + n) * HH, nh, ln);

    vld<12>(gg, g_G3 + n * IOU, ln);
    vld<12>(io, iou3 + n * IOU, ln);
    for (int i = 0; i < 12; i++) nio[i] = io[i] + gg[i];
    for (int i = 0; i < 4; i++) { ip[i] = nio[i]; op[i] = nio[4 + i]; up[i] = nio[8 + i]; }
    sigv<4>(ip); sigv<4>(op); tanhv<4>(up);
    vld<4>(cc, g_c3v + n * HH, ln);
    for (int i = 0; i < 4; i++) nc[i] = ip[i] * up[i] + cc[i];
    vst<4>(out + (5 * NN + n) * HH, nc, ln);
    for (int i = 0; i < 4; i++) nh[i] = op[i] * ftanh(nc[i]);
    vst<4>(out + (4 * NN + n) * HH, nh, ln);
}

// ------------------------- host -------------------------
extern "C" void kernel_launch(void* const* d_in, const int* in_sizes, int n_in,
                              void* d_out, int out_size) {
    const float* x     = (const float*)d_in[0];
    const float* h1    = (const float*)d_in[1];
    const float* c1    = (const float*)d_in[2];
    const float* h2    = (const float*)d_in[3];
    const float* c2    = (const float*)d_in[4];
    const float* h3    = (const float*)d_in[5];
    const float* c3    = (const float*)d_in[6];
    const float* del_t = (const float*)d_in[7];
    const float* iou1  = (const float*)d_in[8];
    const float* iou2  = (const float*)d_in[9];
    const float* iou3  = (const float*)d_in[10];
    const float* Wq_w  = (const float*)d_in[11];
    const float* Wq_b  = (const float*)d_in[12];
    const float* Wc_w  = (const float*)d_in[13];
    const float* Wc_b  = (const float*)d_in[14];
    const float* Uf_w  = (const float*)d_in[15];
    const float* Uf_b  = (const float*)d_in[16];
    const float* Up_w  = (const float*)d_in[17];
    const float* Up_b  = (const float*)d_in[18];
    const float* Uiou_w = (const float*)d_in[19];
    const float* Uiou_b = (const float*)d_in[20];
    const float* dptr  = (const float*)d_in[21];
    const int*   nbr   = (const int*)d_in[22];
    float* out = (float*)d_out;
    (void)in_sizes; (void)n_in; (void)out_size;

    float *pL1, *pL2, *pLc1, *pLc2, *plxp, *plxs;
    float *pA1, *pA2, *pA3, *pF1, *pF2, *pF3, *pC1, *pC2, *pC3, *pQ1, *pQ2, *pQ3;
    float *plhtp, *plhts, *phte, *pG1, *pG2, *pG3;
    cudaGetSymbolAddress((void**)&pL1, g_L1);
    cudaGetSymbolAddress((void**)&pL2, g_L2);
    cudaGetSymbolAddress((void**)&pLc1, g_Lc1);
    cudaGetSymbolAddress((void**)&pLc2, g_Lc2);
    cudaGetSymbolAddress((void**)&plxp, g_lxp);
    cudaGetSymbolAddress((void**)&plxs, g_lxs);
    cudaGetSymbolAddress((void**)&pA1, g_A1);
    cudaGetSymbolAddress((void**)&pA2, g_A2);
    cudaGetSymbolAddress((void**)&pA3, g_A3);
    cudaGetSymbolAddress((void**)&pF1, g_F1);
    cudaGetSymbolAddress((void**)&pF2, g_F2);
    cudaGetSymbolAddress((void**)&pF3, g_F3);
    cudaGetSymbolAddress((void**)&pC1, g_C1);
    cudaGetSymbolAddress((void**)&pC2, g_C2);
    cudaGetSymbolAddress((void**)&pC3, g_C3);
    cudaGetSymbolAddress((void**)&pQ1, g_Q1);
    cudaGetSymbolAddress((void**)&pQ2, g_Q2);
    cudaGetSymbolAddress((void**)&pQ3, g_Q3);
    cudaGetSymbolAddress((void**)&plhtp, g_lhtp);
    cudaGetSymbolAddress((void**)&plhts, g_lhts);
    cudaGetSymbolAddress((void**)&phte, g_hte);
    cudaGetSymbolAddress((void**)&pG1, g_G1);
    cudaGetSymbolAddress((void**)&pG2, g_G2);
    cudaGetSymbolAddress((void**)&pG3, g_G3);

    const int GEMM_SMEM = 4 * GBUF * (int)sizeof(float);
    static int smem_set = 0;
    if (!smem_set) {
        cudaFuncSetAttribute(gemm_tf32, cudaFuncAttributeMaxDynamicSharedMemorySize, GEMM_SMEM);
        smem_set = 1;
    }

    k_prep<<<1024, 256>>>(x, h1, h2, c1, c2);

    GemmJobs jA;
    const float* inA[12] = {pL1, pL2, h3, pL1, pL2, h3, pLc1, pLc2, c3, plxp, plxs, x};
    const float* wA[12]  = {Up_w, Up_w, Up_w, Uf_w, Uf_w, Uf_w, Wc_w, Wc_w, Wc_w, Wq_w, Wq_w, Wq_w};
    const float* bA[12]  = {Up_b, Up_b, Up_b, Uf_b, Uf_b, Uf_b, Wc_b, Wc_b, Wc_b, Wq_b, Wq_b, Wq_b};
    float* cA[12]        = {pA1, pA2, pA3, pF1, pF2, pF3, pC1, pC2, pC3, pQ1, pQ2, pQ3};
    for (int i = 0; i < 12; i++) { jA.A[i] = inA[i]; jA.W[i] = wA[i]; jA.B[i] = bA[i]; jA.C[i] = cA[i]; }
    gemm_tf32<<<dim3(64, 1, 12), 256, GEMM_SMEM>>>(jA, 128);

    k_node<<<1024, 256>>>(h1, h2, h3, c1, c2, c3, del_t, dptr);
    k_score<<<8192, 256>>>(nbr);
    k_attn2<<<1024, 256>>>(nbr);

    GemmJobs jC;
    for (int i = 0; i < 12; i++) { jC.A[i] = plhtp; jC.W[i] = Uiou_w; jC.B[i] = Uiou_b; jC.C[i] = pG1; }
    jC.A[0] = plhtp; jC.C[0] = pG1;
    jC.A[1] = plhts; jC.C[1] = pG2;
    jC.A[2] = phte;  jC.C[2] = pG3;
    gemm_tf32<<<dim3(64, 3, 3), 256, GEMM_SMEM>>>(jC, IOU);

    k_final<<<1024, 256>>>(iou1, iou2, iou3, out);
}